// round 10
// baseline (speedup 1.0000x reference)
#include <cuda_runtime.h>
#include <cuda_bf16.h>
#include <cstdint>

// Problem constants
constexpr int Nn = 50000;
constexpr int D  = 128;
constexpr int E  = 800000;
constexpr int SCAN_B = 512;
constexpr int SCAN_G = (Nn + SCAN_B - 1) / SCAN_B;   // 98

// Scratch (static device globals)
__device__ float g_aggr[(size_t)Nn * D];   // holds h = x + aggr
__device__ float g_t[(size_t)Nn * D];
__device__ float g_stats[2 * D];
__device__ int   g_cnt[Nn];
__device__ int   g_start[Nn];
__device__ int   g_cur[Nn];
__device__ int   g_bsum[SCAN_G];
__device__ uint2 g_perm[E];                // (edge_id, src), sorted by dst
// W1/W2 split bf16 hi/lo, fragment-major for m16n8k16 B-operand
__device__ uint32_t g_Bh[2][8192];
__device__ uint32_t g_Bl[2][8192];

// ---------------------------------------------------------------------------
__global__ void zero_kernel() {
    int i = blockIdx.x * blockDim.x + threadIdx.x;
    if (i < Nn) g_cnt[i] = 0;
    if (i < 2 * D) g_stats[i] = 0.f;
}

// ---------------------------------------------------------------------------
// CSR build: histogram -> 3-step scan -> scatter
// ---------------------------------------------------------------------------
__global__ void hist_kernel(const int* __restrict__ ei) {
    int e = blockIdx.x * blockDim.x + threadIdx.x;
    if (e < E) atomicAdd(&g_cnt[__ldg(ei + E + e)], 1);
}

__global__ void scan1_kernel() {
    __shared__ int sm[SCAN_B];
    int i = blockIdx.x * SCAN_B + threadIdx.x;
    int v = (i < Nn) ? g_cnt[i] : 0;
    sm[threadIdx.x] = v;
    __syncthreads();
#pragma unroll
    for (int off = 1; off < SCAN_B; off <<= 1) {
        int t = (threadIdx.x >= off) ? sm[threadIdx.x - off] : 0;
        __syncthreads();
        sm[threadIdx.x] += t;
        __syncthreads();
    }
    if (i < Nn) g_start[i] = sm[threadIdx.x] - v;
    if (threadIdx.x == SCAN_B - 1) g_bsum[blockIdx.x] = sm[SCAN_B - 1];
}

__global__ void scan2_kernel() {
    if (threadIdx.x == 0) {
        int s = 0;
        for (int b = 0; b < SCAN_G; b++) { int t = g_bsum[b]; g_bsum[b] = s; s += t; }
    }
}

__global__ void scan3_kernel() {
    int i = blockIdx.x * SCAN_B + threadIdx.x;
    if (i < Nn) {
        int s = g_start[i] + g_bsum[blockIdx.x];
        g_start[i] = s;
        g_cur[i]   = s;
    }
}

__global__ void scatter_kernel(const int* __restrict__ ei) {
    int e = blockIdx.x * blockDim.x + threadIdx.x;
    if (e < E) {
        int src = __ldg(ei + e);
        int dst = __ldg(ei + E + e);
        int pos = atomicAdd(&g_cur[dst], 1);
        g_perm[pos] = make_uint2((unsigned)e, (unsigned)src);
    }
}

// ---------------------------------------------------------------------------
// Aggregate: one warp per node. acc = x[i] + sum relu(x[src] + ea[e]).
// ea streamed with __ldcs (evict-first) so the 410MB stream does not evict
// the 25.6MB x working set from L2; x gathers then hit L2. Batch depth 8.
// ---------------------------------------------------------------------------
__global__ __launch_bounds__(256)
void aggregate_kernel(const float* __restrict__ x, const float* __restrict__ ea) {
    int node = (int)(((size_t)blockIdx.x * blockDim.x + threadIdx.x) >> 5);
    int lane = threadIdx.x & 31;
    if (node >= Nn) return;
    const float4* x4  = reinterpret_cast<const float4*>(x);
    const float4* ea4 = reinterpret_cast<const float4*>(ea);
    float4 acc = __ldg(x4 + (size_t)node * 32 + lane);   // seed with x_i
    int start = g_start[node];
    int cnt   = g_cnt[node];
    for (int base = 0; base < cnt; base += 32) {
        int m = cnt - base; if (m > 32) m = 32;
        uint2 p = make_uint2(0u, 0u);
        if (lane < m) p = __ldg(g_perm + start + base + lane);
        for (int j = 0; j < m; j += 8) {
            float4 xs[8], es[8];
#pragma unroll
            for (int u = 0; u < 8; u++) {
                if (j + u < m) {
                    uint32_t e = __shfl_sync(0xffffffffu, p.x, j + u);
                    uint32_t s = __shfl_sync(0xffffffffu, p.y, j + u);
                    xs[u] = __ldg(x4 + (size_t)s * 32 + lane);      // L2-resident
                    es[u] = __ldcs(ea4 + (size_t)e * 32 + lane);    // streaming
                }
            }
#pragma unroll
            for (int u = 0; u < 8; u++) {
                if (j + u < m) {
                    acc.x += fmaxf(xs[u].x + es[u].x, 0.f);
                    acc.y += fmaxf(xs[u].y + es[u].y, 0.f);
                    acc.z += fmaxf(xs[u].z + es[u].z, 0.f);
                    acc.w += fmaxf(xs[u].w + es[u].w, 0.f);
                }
            }
        }
    }
    __stcs(reinterpret_cast<float4*>(g_aggr) + (size_t)node * 32 + lane, acc);
}

// ---------------------------------------------------------------------------
// prep: W -> bf16 hi/lo fragment-major for m16n8k16 B-operand.
// ---------------------------------------------------------------------------
__global__ void prep_kernel(const float* __restrict__ W1, const float* __restrict__ W2) {
    const float* W = blockIdx.x ? W2 : W1;
    uint32_t* bh = g_Bh[blockIdx.x];
    uint32_t* bl = g_Bl[blockIdx.x];
    for (int i = threadIdx.x; i < 64 * 128; i += blockDim.x) {
        int k2 = i >> 7, c = i & 127, k = k2 * 2;
        float w0 = __ldg(W + (size_t)k * D + c);
        float w1 = __ldg(W + (size_t)(k + 1) * D + c);
        __nv_bfloat16 h0 = __float2bfloat16(w0);
        __nv_bfloat16 h1 = __float2bfloat16(w1);
        __nv_bfloat16 l0 = __float2bfloat16(w0 - __bfloat162float(h0));
        __nv_bfloat16 l1 = __float2bfloat16(w1 - __bfloat162float(h1));
        int kstep = k2 >> 3;
        int n16   = c >> 4;
        int lane  = (c & 7) * 4 + (k2 & 3);
        int slot  = 2 * ((c >> 3) & 1) + ((k2 >> 2) & 1);
        int idx   = ((kstep * 8 + n16) * 32 + lane) * 4 + slot;
        bh[idx] = (uint32_t)__bfloat16_as_ushort(h0) | ((uint32_t)__bfloat16_as_ushort(h1) << 16);
        bl[idx] = (uint32_t)__bfloat16_as_ushort(l0) | ((uint32_t)__bfloat16_as_ushort(l1) << 16);
    }
}

// ---------------------------------------------------------------------------
// Tensor-core MLP, 64x128x128 tile per block, 256 threads (8 warps, 2x4 grid),
// 97 KB smem -> 2 blocks/SM for memory/MMA overlap.
//   mode 0: A = g_aggr (= x+aggr); g_t = relu(A@W1 + b1)
//   mode 1: A = g_t;               out = x + A@W2 + b2  (+ BN column stats)
// ---------------------------------------------------------------------------
#define MMA_BF16(d, av, b0, b1) \
    asm volatile("mma.sync.aligned.m16n8k16.row.col.f32.bf16.bf16.f32 " \
                 "{%0,%1,%2,%3},{%4,%5,%6,%7},{%8,%9},{%0,%1,%2,%3};" \
                 : "+f"((d)[0]), "+f"((d)[1]), "+f"((d)[2]), "+f"((d)[3]) \
                 : "r"((av).x), "r"((av).y), "r"((av).z), "r"((av).w), \
                   "r"(b0), "r"(b1))

__global__ __launch_bounds__(256, 2)
void mlp_tc(const float* __restrict__ x, const float* __restrict__ bias,
            float* __restrict__ out, int mode) {
    extern __shared__ __align__(16) unsigned char smem[];
    uint32_t* Ah = reinterpret_cast<uint32_t*>(smem);   // [4096]
    uint32_t* Al = Ah + 4096;                           // [4096]
    uint32_t* Bh = Al + 4096;                           // [8192]
    uint32_t* Bl = Bh + 8192;                           // [8192]
    float* cs = reinterpret_cast<float*>(Bl + 8192);    // [128]
    float* cq = cs + 128;
    const int tid = threadIdx.x, wid = tid >> 5, lane = tid & 31;
    const int r0 = blockIdx.x * 64;

    // B tiles: conflict-free linear copy of pre-packed fragments
    {
        const uint4* sh = reinterpret_cast<const uint4*>(g_Bh[mode]);
        const uint4* sl = reinterpret_cast<const uint4*>(g_Bl[mode]);
        uint4* dh = reinterpret_cast<uint4*>(Bh);
        uint4* dl = reinterpret_cast<uint4*>(Bl);
#pragma unroll
        for (int i = tid; i < 2048; i += 256) { dh[i] = __ldg(sh + i); dl[i] = __ldg(sl + i); }
    }

    // A: load (streaming, read-once) + hi/lo split, packed fragment-major
    // [kstep(8)][m16(4)][lane^kstep(32)][slot(4)] u32
#pragma unroll
    for (int i = tid; i < 2048; i += 256) {
        int r = i >> 5, q = i & 31;
        int gr = r0 + r;
        float4 a = make_float4(0.f, 0.f, 0.f, 0.f);
        if (gr < Nn) {
            const float* src = mode == 0 ? g_aggr : g_t;
            a = __ldcs(reinterpret_cast<const float4*>(src) + (size_t)gr * 32 + q);
        }
        __nv_bfloat16 h0 = __float2bfloat16(a.x), h1 = __float2bfloat16(a.y);
        __nv_bfloat16 h2 = __float2bfloat16(a.z), h3 = __float2bfloat16(a.w);
        __nv_bfloat16 l0 = __float2bfloat16(a.x - __bfloat162float(h0));
        __nv_bfloat16 l1 = __float2bfloat16(a.y - __bfloat162float(h1));
        __nv_bfloat16 l2 = __float2bfloat16(a.z - __bfloat162float(h2));
        __nv_bfloat16 l3 = __float2bfloat16(a.w - __bfloat162float(h3));
        uint32_t hp0 = (uint32_t)__bfloat16_as_ushort(h0) | ((uint32_t)__bfloat16_as_ushort(h1) << 16);
        uint32_t hp1 = (uint32_t)__bfloat16_as_ushort(h2) | ((uint32_t)__bfloat16_as_ushort(h3) << 16);
        uint32_t lp0 = (uint32_t)__bfloat16_as_ushort(l0) | ((uint32_t)__bfloat16_as_ushort(l1) << 16);
        uint32_t lp1 = (uint32_t)__bfloat16_as_ushort(l2) | ((uint32_t)__bfloat16_as_ushort(l3) << 16);
        int kstep = q >> 2;
        int m16   = r >> 4;
        int l     = (r & 7) * 4 + (q & 1) * 2;
        int s     = ((r >> 3) & 1) + 2 * ((q >> 1) & 1);
        int base  = (kstep * 4 + m16) * 32;
        int i0 = (base + ((l)     ^ kstep)) * 4 + s;
        int i1 = (base + ((l + 1) ^ kstep)) * 4 + s;
        Ah[i0] = hp0; Ah[i1] = hp1;
        Al[i0] = lp0; Al[i1] = lp1;
    }
    if (tid < 128) { cs[tid] = 0.f; cq[tid] = 0.f; }
    __syncthreads();

    const int wm = wid & 1, wn = wid >> 1;   // 2x4 warp grid, 32x32 per warp
    float acc[2][2][2][4];
#pragma unroll
    for (int im = 0; im < 2; im++)
#pragma unroll
        for (int in = 0; in < 2; in++)
#pragma unroll
            for (int j = 0; j < 2; j++)
#pragma unroll
                for (int v = 0; v < 4; v++) acc[im][in][j][v] = 0.f;

#pragma unroll
    for (int ks = 0; ks < 8; ks++) {
        uint4 ahv[2], alv[2], bhv[2], blv[2];
#pragma unroll
        for (int im = 0; im < 2; im++) {
            int idx = ((ks * 4 + wm * 2 + im) * 32 + (lane ^ ks)) * 4;
            ahv[im] = *reinterpret_cast<const uint4*>(Ah + idx);
            alv[im] = *reinterpret_cast<const uint4*>(Al + idx);
        }
#pragma unroll
        for (int in = 0; in < 2; in++) {
            int idx = ((ks * 8 + wn * 2 + in) * 32 + lane) * 4;
            bhv[in] = *reinterpret_cast<const uint4*>(Bh + idx);
            blv[in] = *reinterpret_cast<const uint4*>(Bl + idx);
        }
#pragma unroll
        for (int im = 0; im < 2; im++)
#pragma unroll
            for (int in = 0; in < 2; in++)
#pragma unroll
                for (int j = 0; j < 2; j++) {
                    uint32_t b0h = j ? bhv[in].z : bhv[in].x;
                    uint32_t b1h = j ? bhv[in].w : bhv[in].y;
                    uint32_t b0l = j ? blv[in].z : blv[in].x;
                    uint32_t b1l = j ? blv[in].w : blv[in].y;
                    MMA_BF16(acc[im][in][j], ahv[im], b0h, b1h);
                    MMA_BF16(acc[im][in][j], ahv[im], b0l, b1l);
                    MMA_BF16(acc[im][in][j], alv[im], b0h, b1h);
                }
    }

    const int tg = lane >> 2, tc = lane & 3;
    float2 bv[2][2];
#pragma unroll
    for (int in = 0; in < 2; in++)
#pragma unroll
        for (int j = 0; j < 2; j++)
            bv[in][j] = __ldg(reinterpret_cast<const float2*>(bias + wn * 32 + in * 16 + j * 8 + tc * 2));

    if (mode == 0) {
#pragma unroll
        for (int im = 0; im < 2; im++)
#pragma unroll
            for (int rh = 0; rh < 2; rh++) {
                int gr = r0 + (wm * 2 + im) * 16 + rh * 8 + tg;
                if (gr < Nn) {
                    float* op = g_t + (size_t)gr * D;
#pragma unroll
                    for (int in = 0; in < 2; in++)
#pragma unroll
                        for (int j = 0; j < 2; j++) {
                            int col = wn * 32 + in * 16 + j * 8 + tc * 2;
                            float2 v;
                            v.x = fmaxf(acc[im][in][j][rh * 2]     + bv[in][j].x, 0.f);
                            v.y = fmaxf(acc[im][in][j][rh * 2 + 1] + bv[in][j].y, 0.f);
                            *reinterpret_cast<float2*>(op + col) = v;
                        }
                }
            }
    } else {
        float s8[8], q8[8];
#pragma unroll
        for (int u = 0; u < 8; u++) { s8[u] = 0.f; q8[u] = 0.f; }
#pragma unroll
        for (int im = 0; im < 2; im++)
#pragma unroll
            for (int rh = 0; rh < 2; rh++) {
                int gr = r0 + (wm * 2 + im) * 16 + rh * 8 + tg;
                if (gr < Nn) {
                    const float* xr = x + (size_t)gr * D;
                    float* op = out + (size_t)gr * D;
#pragma unroll
                    for (int in = 0; in < 2; in++)
#pragma unroll
                        for (int j = 0; j < 2; j++) {
                            int col = wn * 32 + in * 16 + j * 8 + tc * 2;
                            float2 xv = __ldg(reinterpret_cast<const float2*>(xr + col));
                            float v0 = acc[im][in][j][rh * 2]     + bv[in][j].x + xv.x;
                            float v1 = acc[im][in][j][rh * 2 + 1] + bv[in][j].y + xv.y;
                            int ci = in * 4 + j * 2;
                            s8[ci] += v0;     q8[ci] += v0 * v0;
                            s8[ci + 1] += v1; q8[ci + 1] += v1 * v1;
                            *reinterpret_cast<float2*>(op + col) = make_float2(v0, v1);
                        }
                }
            }
#pragma unroll
        for (int in = 0; in < 2; in++)
#pragma unroll
            for (int j = 0; j < 2; j++)
#pragma unroll
                for (int h = 0; h < 2; h++) {
                    int col = wn * 32 + in * 16 + j * 8 + tc * 2 + h;
                    int ci = in * 4 + j * 2 + h;
                    atomicAdd(&cs[col], s8[ci]);
                    atomicAdd(&cq[col], q8[ci]);
                }
        __syncthreads();
        if (tid < 128) {
            atomicAdd(&g_stats[tid],     cs[tid]);
            atomicAdd(&g_stats[D + tid], cq[tid]);
        }
    }
}

// ---------------------------------------------------------------------------
// BN: compute scale/shift from stats (per block, cheap) then apply in place.
// ---------------------------------------------------------------------------
__global__ void bn_kernel(float* __restrict__ out,
                          const float* __restrict__ bn_w,
                          const float* __restrict__ bn_b) {
    __shared__ float sc_s[D], sh_s[D];
    int tid = threadIdx.x;
    if (tid < D) {
        float inv_n = 1.f / (float)Nn;
        float mean  = g_stats[tid] * inv_n;
        float var   = g_stats[D + tid] * inv_n - mean * mean;
        float rstd  = rsqrtf(var + 1e-5f);
        float sc    = rstd * __ldg(bn_w + tid);
        sc_s[tid] = sc;
        sh_s[tid] = __ldg(bn_b + tid) - mean * sc;
    }
    __syncthreads();
    size_t stride = (size_t)gridDim.x * blockDim.x;
    size_t total  = (size_t)Nn * 32;
    for (size_t v = (size_t)blockIdx.x * blockDim.x + tid; v < total; v += stride) {
        int q = (int)(v & 31);
        float4 h = reinterpret_cast<float4*>(out)[v];
        float4 sc = *reinterpret_cast<const float4*>(sc_s + q * 4);
        float4 sh = *reinterpret_cast<const float4*>(sh_s + q * 4);
        h.x = h.x * sc.x + sh.x;
        h.y = h.y * sc.y + sh.y;
        h.z = h.z * sc.z + sh.z;
        h.w = h.w * sc.w + sh.w;
        reinterpret_cast<float4*>(out)[v] = h;
    }
}

// ---------------------------------------------------------------------------
extern "C" void kernel_launch(void* const* d_in, const int* in_sizes, int n_in,
                              void* d_out, int out_size) {
    const float* x   = (const float*)d_in[0];
    const int*   ei  = (const int*)d_in[1];
    const float* ea  = (const float*)d_in[2];
    const float* W1  = (const float*)d_in[3];
    const float* b1  = (const float*)d_in[4];
    const float* W2  = (const float*)d_in[5];
    const float* b2  = (const float*)d_in[6];
    const float* bnw = (const float*)d_in[7];
    const float* bnb = (const float*)d_in[8];
    float* out = (float*)d_out;

    zero_kernel<<<(Nn + 255) / 256, 256>>>();
    prep_kernel<<<2, 256>>>(W1, W2);
    hist_kernel<<<(E + 255) / 256, 256>>>(ei);
    scan1_kernel<<<SCAN_G, SCAN_B>>>();
    scan2_kernel<<<1, 32>>>();
    scan3_kernel<<<SCAN_G, SCAN_B>>>();
    scatter_kernel<<<(E + 255) / 256, 256>>>(ei);
    aggregate_kernel<<<(Nn * 32 + 255) / 256, 256>>>(x, ea);

    int smem_bytes = (4096 * 2 + 8192 * 2 + 256) * 4;   // 99,328 B
    cudaFuncSetAttribute(mlp_tc, cudaFuncAttributeMaxDynamicSharedMemorySize, smem_bytes);
    int grid = (Nn + 63) / 64;
    mlp_tc<<<grid, 256, smem_bytes>>>(x, b1, nullptr, 0);
    mlp_tc<<<grid, 256, smem_bytes>>>(x, b2, out, 1);

    bn_kernel<<<1024, 256>>>(out, bnw, bnb);
}

// round 11
// speedup vs baseline: 1.7111x; 1.7111x over previous
#include <cuda_runtime.h>
#include <cuda_bf16.h>
#include <cstdint>

// Problem constants
constexpr int Nn = 50000;
constexpr int D  = 128;
constexpr int E  = 800000;
constexpr int SCAN_B = 512;
constexpr int SCAN_G = (Nn + SCAN_B - 1) / SCAN_B;   // 98

// Scratch (static device globals)
__device__ float g_aggr[(size_t)Nn * D];   // holds h = x + aggr
__device__ float g_t[(size_t)Nn * D];
__device__ float g_stats[2 * D];
__device__ int   g_cnt[Nn];
__device__ int   g_start[Nn];
__device__ int   g_cur[Nn];
__device__ int   g_bsum[SCAN_G];
__device__ uint2 g_perm[E];                // (edge_id, src), sorted by dst
// W1/W2 split bf16 hi/lo, fragment-major for m16n8k16 B-operand
__device__ uint32_t g_Bh[2][8192];
__device__ uint32_t g_Bl[2][8192];

// ---------------------------------------------------------------------------
__global__ void zero_kernel() {
    int i = blockIdx.x * blockDim.x + threadIdx.x;
    if (i < Nn) g_cnt[i] = 0;
    if (i < 2 * D) g_stats[i] = 0.f;
}

// ---------------------------------------------------------------------------
// CSR build: histogram -> 3-step scan -> scatter
// ---------------------------------------------------------------------------
__global__ void hist_kernel(const int* __restrict__ ei) {
    int e = blockIdx.x * blockDim.x + threadIdx.x;
    if (e < E) atomicAdd(&g_cnt[__ldg(ei + E + e)], 1);
}

__global__ void scan1_kernel() {
    __shared__ int sm[SCAN_B];
    int i = blockIdx.x * SCAN_B + threadIdx.x;
    int v = (i < Nn) ? g_cnt[i] : 0;
    sm[threadIdx.x] = v;
    __syncthreads();
#pragma unroll
    for (int off = 1; off < SCAN_B; off <<= 1) {
        int t = (threadIdx.x >= off) ? sm[threadIdx.x - off] : 0;
        __syncthreads();
        sm[threadIdx.x] += t;
        __syncthreads();
    }
    if (i < Nn) g_start[i] = sm[threadIdx.x] - v;
    if (threadIdx.x == SCAN_B - 1) g_bsum[blockIdx.x] = sm[SCAN_B - 1];
}

__global__ void scan2_kernel() {
    if (threadIdx.x == 0) {
        int s = 0;
        for (int b = 0; b < SCAN_G; b++) { int t = g_bsum[b]; g_bsum[b] = s; s += t; }
    }
}

__global__ void scan3_kernel() {
    int i = blockIdx.x * SCAN_B + threadIdx.x;
    if (i < Nn) {
        int s = g_start[i] + g_bsum[blockIdx.x];
        g_start[i] = s;
        g_cur[i]   = s;
    }
}

__global__ void scatter_kernel(const int* __restrict__ ei) {
    int e = blockIdx.x * blockDim.x + threadIdx.x;
    if (e < E) {
        int src = __ldg(ei + e);
        int dst = __ldg(ei + E + e);
        int pos = atomicAdd(&g_cur[dst], 1);
        g_perm[pos] = make_uint2((unsigned)e, (unsigned)src);
    }
}

// ---------------------------------------------------------------------------
// Aggregate: one warp per node. acc = x[i] + sum relu(x[src] + ea[e]).
// R5 structure verbatim (low regs, high occupancy). Single change: ea loads
// use __ldcs (evict-first) so the 410MB read-once stream does not thrash the
// 25.6MB x working set out of L2 -> x gathers hit L2 instead of DRAM.
// ---------------------------------------------------------------------------
__global__ __launch_bounds__(256)
void aggregate_kernel(const float* __restrict__ x, const float* __restrict__ ea) {
    int node = (int)(((size_t)blockIdx.x * blockDim.x + threadIdx.x) >> 5);
    int lane = threadIdx.x & 31;
    if (node >= Nn) return;
    const float4* x4  = reinterpret_cast<const float4*>(x);
    const float4* ea4 = reinterpret_cast<const float4*>(ea);
    float4 acc = __ldg(x4 + (size_t)node * 32 + lane);   // seed with x_i
    int start = g_start[node];
    int cnt   = g_cnt[node];
    for (int base = 0; base < cnt; base += 32) {
        int m = cnt - base; if (m > 32) m = 32;
        uint2 p = make_uint2(0u, 0u);
        if (lane < m) p = __ldg(g_perm + start + base + lane);
        for (int j = 0; j < m; j += 4) {
#pragma unroll
            for (int u = 0; u < 4; u++) {
                if (j + u < m) {
                    uint32_t e = __shfl_sync(0xffffffffu, p.x, j + u);
                    uint32_t s = __shfl_sync(0xffffffffu, p.y, j + u);
                    float4 xv = __ldg(x4 + (size_t)s * 32 + lane);     // L2-resident
                    float4 ev = __ldcs(ea4 + (size_t)e * 32 + lane);   // streaming
                    acc.x += fmaxf(xv.x + ev.x, 0.f);
                    acc.y += fmaxf(xv.y + ev.y, 0.f);
                    acc.z += fmaxf(xv.z + ev.z, 0.f);
                    acc.w += fmaxf(xv.w + ev.w, 0.f);
                }
            }
        }
    }
    *(reinterpret_cast<float4*>(g_aggr) + (size_t)node * 32 + lane) = acc;
}

// ---------------------------------------------------------------------------
// prep: W -> bf16 hi/lo fragment-major for m16n8k16 B-operand.
// ---------------------------------------------------------------------------
__global__ void prep_kernel(const float* __restrict__ W1, const float* __restrict__ W2) {
    const float* W = blockIdx.x ? W2 : W1;
    uint32_t* bh = g_Bh[blockIdx.x];
    uint32_t* bl = g_Bl[blockIdx.x];
    for (int i = threadIdx.x; i < 64 * 128; i += blockDim.x) {
        int k2 = i >> 7, c = i & 127, k = k2 * 2;
        float w0 = __ldg(W + (size_t)k * D + c);
        float w1 = __ldg(W + (size_t)(k + 1) * D + c);
        __nv_bfloat16 h0 = __float2bfloat16(w0);
        __nv_bfloat16 h1 = __float2bfloat16(w1);
        __nv_bfloat16 l0 = __float2bfloat16(w0 - __bfloat162float(h0));
        __nv_bfloat16 l1 = __float2bfloat16(w1 - __bfloat162float(h1));
        int kstep = k2 >> 3;
        int n16   = c >> 4;
        int lane  = (c & 7) * 4 + (k2 & 3);
        int slot  = 2 * ((c >> 3) & 1) + ((k2 >> 2) & 1);
        int idx   = ((kstep * 8 + n16) * 32 + lane) * 4 + slot;
        bh[idx] = (uint32_t)__bfloat16_as_ushort(h0) | ((uint32_t)__bfloat16_as_ushort(h1) << 16);
        bl[idx] = (uint32_t)__bfloat16_as_ushort(l0) | ((uint32_t)__bfloat16_as_ushort(l1) << 16);
    }
}

// ---------------------------------------------------------------------------
// Tensor-core MLP, 64x128x128 tile per block, 256 threads (8 warps, 2x4 grid),
// 97 KB smem -> 2 blocks/SM for memory/MMA overlap.
//   mode 0: A = g_aggr (= x+aggr); g_t = relu(A@W1 + b1)
//   mode 1: A = g_t;               out = x + A@W2 + b2  (+ BN column stats)
// ---------------------------------------------------------------------------
#define MMA_BF16(d, av, b0, b1) \
    asm volatile("mma.sync.aligned.m16n8k16.row.col.f32.bf16.bf16.f32 " \
                 "{%0,%1,%2,%3},{%4,%5,%6,%7},{%8,%9},{%0,%1,%2,%3};" \
                 : "+f"((d)[0]), "+f"((d)[1]), "+f"((d)[2]), "+f"((d)[3]) \
                 : "r"((av).x), "r"((av).y), "r"((av).z), "r"((av).w), \
                   "r"(b0), "r"(b1))

__global__ __launch_bounds__(256, 2)
void mlp_tc(const float* __restrict__ x, const float* __restrict__ bias,
            float* __restrict__ out, int mode) {
    extern __shared__ __align__(16) unsigned char smem[];
    uint32_t* Ah = reinterpret_cast<uint32_t*>(smem);   // [4096]
    uint32_t* Al = Ah + 4096;                           // [4096]
    uint32_t* Bh = Al + 4096;                           // [8192]
    uint32_t* Bl = Bh + 8192;                           // [8192]
    float* cs = reinterpret_cast<float*>(Bl + 8192);    // [128]
    float* cq = cs + 128;
    const int tid = threadIdx.x, wid = tid >> 5, lane = tid & 31;
    const int r0 = blockIdx.x * 64;

    // B tiles: conflict-free linear copy of pre-packed fragments
    {
        const uint4* sh = reinterpret_cast<const uint4*>(g_Bh[mode]);
        const uint4* sl = reinterpret_cast<const uint4*>(g_Bl[mode]);
        uint4* dh = reinterpret_cast<uint4*>(Bh);
        uint4* dl = reinterpret_cast<uint4*>(Bl);
#pragma unroll
        for (int i = tid; i < 2048; i += 256) { dh[i] = __ldg(sh + i); dl[i] = __ldg(sl + i); }
    }

    // A: load + hi/lo split, packed fragment-major
    // [kstep(8)][m16(4)][lane^kstep(32)][slot(4)] u32
#pragma unroll
    for (int i = tid; i < 2048; i += 256) {
        int r = i >> 5, q = i & 31;
        int gr = r0 + r;
        float4 a = make_float4(0.f, 0.f, 0.f, 0.f);
        if (gr < Nn) {
            const float* src = mode == 0 ? g_aggr : g_t;
            a = *(reinterpret_cast<const float4*>(src) + (size_t)gr * 32 + q);
        }
        __nv_bfloat16 h0 = __float2bfloat16(a.x), h1 = __float2bfloat16(a.y);
        __nv_bfloat16 h2 = __float2bfloat16(a.z), h3 = __float2bfloat16(a.w);
        __nv_bfloat16 l0 = __float2bfloat16(a.x - __bfloat162float(h0));
        __nv_bfloat16 l1 = __float2bfloat16(a.y - __bfloat162float(h1));
        __nv_bfloat16 l2 = __float2bfloat16(a.z - __bfloat162float(h2));
        __nv_bfloat16 l3 = __float2bfloat16(a.w - __bfloat162float(h3));
        uint32_t hp0 = (uint32_t)__bfloat16_as_ushort(h0) | ((uint32_t)__bfloat16_as_ushort(h1) << 16);
        uint32_t hp1 = (uint32_t)__bfloat16_as_ushort(h2) | ((uint32_t)__bfloat16_as_ushort(h3) << 16);
        uint32_t lp0 = (uint32_t)__bfloat16_as_ushort(l0) | ((uint32_t)__bfloat16_as_ushort(l1) << 16);
        uint32_t lp1 = (uint32_t)__bfloat16_as_ushort(l2) | ((uint32_t)__bfloat16_as_ushort(l3) << 16);
        int kstep = q >> 2;
        int m16   = r >> 4;
        int l     = (r & 7) * 4 + (q & 1) * 2;
        int s     = ((r >> 3) & 1) + 2 * ((q >> 1) & 1);
        int base  = (kstep * 4 + m16) * 32;
        int i0 = (base + ((l)     ^ kstep)) * 4 + s;
        int i1 = (base + ((l + 1) ^ kstep)) * 4 + s;
        Ah[i0] = hp0; Ah[i1] = hp1;
        Al[i0] = lp0; Al[i1] = lp1;
    }
    if (tid < 128) { cs[tid] = 0.f; cq[tid] = 0.f; }
    __syncthreads();

    const int wm = wid & 1, wn = wid >> 1;   // 2x4 warp grid, 32x32 per warp
    float acc[2][2][2][4];
#pragma unroll
    for (int im = 0; im < 2; im++)
#pragma unroll
        for (int in = 0; in < 2; in++)
#pragma unroll
            for (int j = 0; j < 2; j++)
#pragma unroll
                for (int v = 0; v < 4; v++) acc[im][in][j][v] = 0.f;

#pragma unroll
    for (int ks = 0; ks < 8; ks++) {
        uint4 ahv[2], alv[2], bhv[2], blv[2];
#pragma unroll
        for (int im = 0; im < 2; im++) {
            int idx = ((ks * 4 + wm * 2 + im) * 32 + (lane ^ ks)) * 4;
            ahv[im] = *reinterpret_cast<const uint4*>(Ah + idx);
            alv[im] = *reinterpret_cast<const uint4*>(Al + idx);
        }
#pragma unroll
        for (int in = 0; in < 2; in++) {
            int idx = ((ks * 8 + wn * 2 + in) * 32 + lane) * 4;
            bhv[in] = *reinterpret_cast<const uint4*>(Bh + idx);
            blv[in] = *reinterpret_cast<const uint4*>(Bl + idx);
        }
#pragma unroll
        for (int im = 0; im < 2; im++)
#pragma unroll
            for (int in = 0; in < 2; in++)
#pragma unroll
                for (int j = 0; j < 2; j++) {
                    uint32_t b0h = j ? bhv[in].z : bhv[in].x;
                    uint32_t b1h = j ? bhv[in].w : bhv[in].y;
                    uint32_t b0l = j ? blv[in].z : blv[in].x;
                    uint32_t b1l = j ? blv[in].w : blv[in].y;
                    MMA_BF16(acc[im][in][j], ahv[im], b0h, b1h);
                    MMA_BF16(acc[im][in][j], ahv[im], b0l, b1l);
                    MMA_BF16(acc[im][in][j], alv[im], b0h, b1h);
                }
    }

    const int tg = lane >> 2, tc = lane & 3;
    float2 bv[2][2];
#pragma unroll
    for (int in = 0; in < 2; in++)
#pragma unroll
        for (int j = 0; j < 2; j++)
            bv[in][j] = __ldg(reinterpret_cast<const float2*>(bias + wn * 32 + in * 16 + j * 8 + tc * 2));

    if (mode == 0) {
#pragma unroll
        for (int im = 0; im < 2; im++)
#pragma unroll
            for (int rh = 0; rh < 2; rh++) {
                int gr = r0 + (wm * 2 + im) * 16 + rh * 8 + tg;
                if (gr < Nn) {
                    float* op = g_t + (size_t)gr * D;
#pragma unroll
                    for (int in = 0; in < 2; in++)
#pragma unroll
                        for (int j = 0; j < 2; j++) {
                            int col = wn * 32 + in * 16 + j * 8 + tc * 2;
                            float2 v;
                            v.x = fmaxf(acc[im][in][j][rh * 2]     + bv[in][j].x, 0.f);
                            v.y = fmaxf(acc[im][in][j][rh * 2 + 1] + bv[in][j].y, 0.f);
                            *reinterpret_cast<float2*>(op + col) = v;
                        }
                }
            }
    } else {
        float s8[8], q8[8];
#pragma unroll
        for (int u = 0; u < 8; u++) { s8[u] = 0.f; q8[u] = 0.f; }
#pragma unroll
        for (int im = 0; im < 2; im++)
#pragma unroll
            for (int rh = 0; rh < 2; rh++) {
                int gr = r0 + (wm * 2 + im) * 16 + rh * 8 + tg;
                if (gr < Nn) {
                    const float* xr = x + (size_t)gr * D;
                    float* op = out + (size_t)gr * D;
#pragma unroll
                    for (int in = 0; in < 2; in++)
#pragma unroll
                        for (int j = 0; j < 2; j++) {
                            int col = wn * 32 + in * 16 + j * 8 + tc * 2;
                            float2 xv = __ldg(reinterpret_cast<const float2*>(xr + col));
                            float v0 = acc[im][in][j][rh * 2]     + bv[in][j].x + xv.x;
                            float v1 = acc[im][in][j][rh * 2 + 1] + bv[in][j].y + xv.y;
                            int ci = in * 4 + j * 2;
                            s8[ci] += v0;     q8[ci] += v0 * v0;
                            s8[ci + 1] += v1; q8[ci + 1] += v1 * v1;
                            *reinterpret_cast<float2*>(op + col) = make_float2(v0, v1);
                        }
                }
            }
#pragma unroll
        for (int in = 0; in < 2; in++)
#pragma unroll
            for (int j = 0; j < 2; j++)
#pragma unroll
                for (int h = 0; h < 2; h++) {
                    int col = wn * 32 + in * 16 + j * 8 + tc * 2 + h;
                    int ci = in * 4 + j * 2 + h;
                    atomicAdd(&cs[col], s8[ci]);
                    atomicAdd(&cq[col], q8[ci]);
                }
        __syncthreads();
        if (tid < 128) {
            atomicAdd(&g_stats[tid],     cs[tid]);
            atomicAdd(&g_stats[D + tid], cq[tid]);
        }
    }
}

// ---------------------------------------------------------------------------
// BN: compute scale/shift from stats (per block, cheap) then apply in place.
// ---------------------------------------------------------------------------
__global__ void bn_kernel(float* __restrict__ out,
                          const float* __restrict__ bn_w,
                          const float* __restrict__ bn_b) {
    __shared__ float sc_s[D], sh_s[D];
    int tid = threadIdx.x;
    if (tid < D) {
        float inv_n = 1.f / (float)Nn;
        float mean  = g_stats[tid] * inv_n;
        float var   = g_stats[D + tid] * inv_n - mean * mean;
        float rstd  = rsqrtf(var + 1e-5f);
        float sc    = rstd * __ldg(bn_w + tid);
        sc_s[tid] = sc;
        sh_s[tid] = __ldg(bn_b + tid) - mean * sc;
    }
    __syncthreads();
    size_t stride = (size_t)gridDim.x * blockDim.x;
    size_t total  = (size_t)Nn * 32;
    for (size_t v = (size_t)blockIdx.x * blockDim.x + tid; v < total; v += stride) {
        int q = (int)(v & 31);
        float4 h = reinterpret_cast<float4*>(out)[v];
        float4 sc = *reinterpret_cast<const float4*>(sc_s + q * 4);
        float4 sh = *reinterpret_cast<const float4*>(sh_s + q * 4);
        h.x = h.x * sc.x + sh.x;
        h.y = h.y * sc.y + sh.y;
        h.z = h.z * sc.z + sh.z;
        h.w = h.w * sc.w + sh.w;
        reinterpret_cast<float4*>(out)[v] = h;
    }
}

// ---------------------------------------------------------------------------
extern "C" void kernel_launch(void* const* d_in, const int* in_sizes, int n_in,
                              void* d_out, int out_size) {
    const float* x   = (const float*)d_in[0];
    const int*   ei  = (const int*)d_in[1];
    const float* ea  = (const float*)d_in[2];
    const float* W1  = (const float*)d_in[3];
    const float* b1  = (const float*)d_in[4];
    const float* W2  = (const float*)d_in[5];
    const float* b2  = (const float*)d_in[6];
    const float* bnw = (const float*)d_in[7];
    const float* bnb = (const float*)d_in[8];
    float* out = (float*)d_out;

    zero_kernel<<<(Nn + 255) / 256, 256>>>();
    prep_kernel<<<2, 256>>>(W1, W2);
    hist_kernel<<<(E + 255) / 256, 256>>>(ei);
    scan1_kernel<<<SCAN_G, SCAN_B>>>();
    scan2_kernel<<<1, 32>>>();
    scan3_kernel<<<SCAN_G, SCAN_B>>>();
    scatter_kernel<<<(E + 255) / 256, 256>>>(ei);
    aggregate_kernel<<<(Nn * 32 + 255) / 256, 256>>>(x, ea);

    int smem_bytes = (4096 * 2 + 8192 * 2 + 256) * 4;   // 99,328 B
    cudaFuncSetAttribute(mlp_tc, cudaFuncAttributeMaxDynamicSharedMemorySize, smem_bytes);
    int grid = (Nn + 63) / 64;
    mlp_tc<<<grid, 256, smem_bytes>>>(x, b1, nullptr, 0);
    mlp_tc<<<grid, 256, smem_bytes>>>(x, b2, out, 1);

    bn_kernel<<<1024, 256>>>(out, bnw, bnb);
}

// round 12
// speedup vs baseline: 1.7587x; 1.0278x over previous
#include <cuda_runtime.h>
#include <cuda_bf16.h>
#include <cstdint>

// Problem constants
constexpr int Nn = 50000;
constexpr int D  = 128;
constexpr int E  = 800000;
constexpr int SCAN_B = 512;
constexpr int SCAN_G = (Nn + SCAN_B - 1) / SCAN_B;   // 98

// Scratch (static device globals)
__device__ float g_aggr[(size_t)Nn * D];   // holds h = x + aggr
__device__ float g_t[(size_t)Nn * D];
__device__ float g_stats[2 * D];
__device__ int   g_cnt[Nn];
__device__ int   g_start[Nn];
__device__ int   g_cur[Nn];
__device__ int   g_desc[SCAN_G];           // decoupled-lookback descriptors
__device__ uint2 g_perm[E];                // (edge_id, src), sorted by dst
// W1/W2 split bf16 hi/lo, fragment-major for m16n8k16 B-operand
__device__ uint32_t g_Bh[2][8192];
__device__ uint32_t g_Bl[2][8192];

// ---------------------------------------------------------------------------
// init: blocks 0-1 pack W1/W2 (bf16 hi/lo fragment-major); blocks 2+ zero
// g_cnt / g_stats / g_desc. One launch replaces zero+prep.
// ---------------------------------------------------------------------------
__global__ void init_kernel(const float* __restrict__ W1, const float* __restrict__ W2) {
    if (blockIdx.x < 2) {
        const float* W = blockIdx.x ? W2 : W1;
        uint32_t* bh = g_Bh[blockIdx.x];
        uint32_t* bl = g_Bl[blockIdx.x];
        for (int i = threadIdx.x; i < 64 * 128; i += blockDim.x) {
            int k2 = i >> 7, c = i & 127, k = k2 * 2;
            float w0 = __ldg(W + (size_t)k * D + c);
            float w1 = __ldg(W + (size_t)(k + 1) * D + c);
            __nv_bfloat16 h0 = __float2bfloat16(w0);
            __nv_bfloat16 h1 = __float2bfloat16(w1);
            __nv_bfloat16 l0 = __float2bfloat16(w0 - __bfloat162float(h0));
            __nv_bfloat16 l1 = __float2bfloat16(w1 - __bfloat162float(h1));
            int kstep = k2 >> 3;
            int n16   = c >> 4;
            int lane  = (c & 7) * 4 + (k2 & 3);
            int slot  = 2 * ((c >> 3) & 1) + ((k2 >> 2) & 1);
            int idx   = ((kstep * 8 + n16) * 32 + lane) * 4 + slot;
            bh[idx] = (uint32_t)__bfloat16_as_ushort(h0) | ((uint32_t)__bfloat16_as_ushort(h1) << 16);
            bl[idx] = (uint32_t)__bfloat16_as_ushort(l0) | ((uint32_t)__bfloat16_as_ushort(l1) << 16);
        }
    } else {
        int i = (blockIdx.x - 2) * blockDim.x + threadIdx.x;
        if (i < Nn) g_cnt[i] = 0;
        if (i < 2 * D) g_stats[i] = 0.f;
        if (i < SCAN_G) g_desc[i] = 0;
    }
}

// ---------------------------------------------------------------------------
__global__ void hist_kernel(const int* __restrict__ ei) {
    int e = blockIdx.x * blockDim.x + threadIdx.x;
    if (e < E) atomicAdd(&g_cnt[__ldg(ei + E + e)], 1);
}

// ---------------------------------------------------------------------------
// Single-kernel exclusive scan over g_cnt via decoupled lookback.
// Descriptor: (sum << 2) | flag;  flag 1 = block aggregate, 2 = inclusive
// prefix. Sums <= E = 800000 so << 2 cannot overflow. Blocks launch in
// bid order on B300 wave 1, so waiting on predecessors cannot deadlock
// (98 blocks <= 148 SMs; all co-resident regardless).
// ---------------------------------------------------------------------------
__global__ __launch_bounds__(SCAN_B)
void scan_kernel() {
    __shared__ int sm[SCAN_B];
    __shared__ int s_prefix;
    const int b = blockIdx.x;
    const int t = threadIdx.x;
    int i = b * SCAN_B + t;
    int v = (i < Nn) ? g_cnt[i] : 0;
    sm[t] = v;
    __syncthreads();
#pragma unroll
    for (int off = 1; off < SCAN_B; off <<= 1) {
        int tmp = (t >= off) ? sm[t - off] : 0;
        __syncthreads();
        sm[t] += tmp;
        __syncthreads();
    }
    int total = sm[SCAN_B - 1];

    if (b == 0) {
        if (t == 0) {
            atomicExch(&g_desc[0], (total << 2) | 2);
            s_prefix = 0;
        }
    } else {
        if (t == 0) atomicExch(&g_desc[b], (total << 2) | 1);  // publish aggregate
        if (t < 32) {
            int prefix = 0, offset = 0;
            bool done = false;
            while (!done) {
                int j = b - 1 - offset - t;
                int d;
                if (j >= 0) {
                    do { d = atomicAdd(&g_desc[j], 0); } while ((d & 3) == 0);
                } else {
                    d = 2;   // virtual block: prefix 0
                }
                unsigned mask = __ballot_sync(0xffffffffu, (d & 3) == 2);
                int contrib;
                if (mask) {
                    int firstP = __ffs(mask) - 1;     // nearest lane with a prefix
                    contrib = (t <= firstP) ? (d >> 2) : 0;
                    done = true;
                } else {
                    contrib = d >> 2;                 // all aggregates, keep walking
                }
#pragma unroll
                for (int o = 16; o; o >>= 1) contrib += __shfl_xor_sync(0xffffffffu, contrib, o);
                prefix += contrib;
                offset += 32;
            }
            if (t == 0) {
                atomicExch(&g_desc[b], ((prefix + total) << 2) | 2);
                s_prefix = prefix;
            }
        }
    }
    __syncthreads();
    int s = sm[t] - v + s_prefix;
    if (i < Nn) { g_start[i] = s; g_cur[i] = s; }
}

// ---------------------------------------------------------------------------
__global__ void scatter_kernel(const int* __restrict__ ei) {
    int e = blockIdx.x * blockDim.x + threadIdx.x;
    if (e < E) {
        int src = __ldg(ei + e);
        int dst = __ldg(ei + E + e);
        int pos = atomicAdd(&g_cur[dst], 1);
        g_perm[pos] = make_uint2((unsigned)e, (unsigned)src);
    }
}

// ---------------------------------------------------------------------------
// Aggregate: one warp per node. acc = x[i] + sum relu(x[src] + ea[e]).
// ea via __ldcs (evict-first streaming) so the 410MB read-once stream does
// not thrash the 25.6MB x working set out of L2. Identical to the 212.7us
// version.
// ---------------------------------------------------------------------------
__global__ __launch_bounds__(256)
void aggregate_kernel(const float* __restrict__ x, const float* __restrict__ ea) {
    int node = (int)(((size_t)blockIdx.x * blockDim.x + threadIdx.x) >> 5);
    int lane = threadIdx.x & 31;
    if (node >= Nn) return;
    const float4* x4  = reinterpret_cast<const float4*>(x);
    const float4* ea4 = reinterpret_cast<const float4*>(ea);
    float4 acc = __ldg(x4 + (size_t)node * 32 + lane);   // seed with x_i
    int start = g_start[node];
    int cnt   = g_cnt[node];
    for (int base = 0; base < cnt; base += 32) {
        int m = cnt - base; if (m > 32) m = 32;
        uint2 p = make_uint2(0u, 0u);
        if (lane < m) p = __ldg(g_perm + start + base + lane);
        for (int j = 0; j < m; j += 4) {
#pragma unroll
            for (int u = 0; u < 4; u++) {
                if (j + u < m) {
                    uint32_t e = __shfl_sync(0xffffffffu, p.x, j + u);
                    uint32_t s = __shfl_sync(0xffffffffu, p.y, j + u);
                    float4 xv = __ldg(x4 + (size_t)s * 32 + lane);     // L2-resident
                    float4 ev = __ldcs(ea4 + (size_t)e * 32 + lane);   // streaming
                    acc.x += fmaxf(xv.x + ev.x, 0.f);
                    acc.y += fmaxf(xv.y + ev.y, 0.f);
                    acc.z += fmaxf(xv.z + ev.z, 0.f);
                    acc.w += fmaxf(xv.w + ev.w, 0.f);
                }
            }
        }
    }
    *(reinterpret_cast<float4*>(g_aggr) + (size_t)node * 32 + lane) = acc;
}

// ---------------------------------------------------------------------------
// Tensor-core MLP, 64x128x128 tile per block, 256 threads (8 warps, 2x4 grid),
// 97 KB smem -> 2 blocks/SM for memory/MMA overlap. Identical to 212.7us ver.
//   mode 0: A = g_aggr (= x+aggr); g_t = relu(A@W1 + b1)
//   mode 1: A = g_t;               out = x + A@W2 + b2  (+ BN column stats)
// ---------------------------------------------------------------------------
#define MMA_BF16(d, av, b0, b1) \
    asm volatile("mma.sync.aligned.m16n8k16.row.col.f32.bf16.bf16.f32 " \
                 "{%0,%1,%2,%3},{%4,%5,%6,%7},{%8,%9},{%0,%1,%2,%3};" \
                 : "+f"((d)[0]), "+f"((d)[1]), "+f"((d)[2]), "+f"((d)[3]) \
                 : "r"((av).x), "r"((av).y), "r"((av).z), "r"((av).w), \
                   "r"(b0), "r"(b1))

__global__ __launch_bounds__(256, 2)
void mlp_tc(const float* __restrict__ x, const float* __restrict__ bias,
            float* __restrict__ out, int mode) {
    extern __shared__ __align__(16) unsigned char smem[];
    uint32_t* Ah = reinterpret_cast<uint32_t*>(smem);   // [4096]
    uint32_t* Al = Ah + 4096;                           // [4096]
    uint32_t* Bh = Al + 4096;                           // [8192]
    uint32_t* Bl = Bh + 8192;                           // [8192]
    float* cs = reinterpret_cast<float*>(Bl + 8192);    // [128]
    float* cq = cs + 128;
    const int tid = threadIdx.x, wid = tid >> 5, lane = tid & 31;
    const int r0 = blockIdx.x * 64;

    {
        const uint4* sh = reinterpret_cast<const uint4*>(g_Bh[mode]);
        const uint4* sl = reinterpret_cast<const uint4*>(g_Bl[mode]);
        uint4* dh = reinterpret_cast<uint4*>(Bh);
        uint4* dl = reinterpret_cast<uint4*>(Bl);
#pragma unroll
        for (int i = tid; i < 2048; i += 256) { dh[i] = __ldg(sh + i); dl[i] = __ldg(sl + i); }
    }

#pragma unroll
    for (int i = tid; i < 2048; i += 256) {
        int r = i >> 5, q = i & 31;
        int gr = r0 + r;
        float4 a = make_float4(0.f, 0.f, 0.f, 0.f);
        if (gr < Nn) {
            const float* src = mode == 0 ? g_aggr : g_t;
            a = *(reinterpret_cast<const float4*>(src) + (size_t)gr * 32 + q);
        }
        __nv_bfloat16 h0 = __float2bfloat16(a.x), h1 = __float2bfloat16(a.y);
        __nv_bfloat16 h2 = __float2bfloat16(a.z), h3 = __float2bfloat16(a.w);
        __nv_bfloat16 l0 = __float2bfloat16(a.x - __bfloat162float(h0));
        __nv_bfloat16 l1 = __float2bfloat16(a.y - __bfloat162float(h1));
        __nv_bfloat16 l2 = __float2bfloat16(a.z - __bfloat162float(h2));
        __nv_bfloat16 l3 = __float2bfloat16(a.w - __bfloat162float(h3));
        uint32_t hp0 = (uint32_t)__bfloat16_as_ushort(h0) | ((uint32_t)__bfloat16_as_ushort(h1) << 16);
        uint32_t hp1 = (uint32_t)__bfloat16_as_ushort(h2) | ((uint32_t)__bfloat16_as_ushort(h3) << 16);
        uint32_t lp0 = (uint32_t)__bfloat16_as_ushort(l0) | ((uint32_t)__bfloat16_as_ushort(l1) << 16);
        uint32_t lp1 = (uint32_t)__bfloat16_as_ushort(l2) | ((uint32_t)__bfloat16_as_ushort(l3) << 16);
        int kstep = q >> 2;
        int m16   = r >> 4;
        int l     = (r & 7) * 4 + (q & 1) * 2;
        int s     = ((r >> 3) & 1) + 2 * ((q >> 1) & 1);
        int base  = (kstep * 4 + m16) * 32;
        int i0 = (base + ((l)     ^ kstep)) * 4 + s;
        int i1 = (base + ((l + 1) ^ kstep)) * 4 + s;
        Ah[i0] = hp0; Ah[i1] = hp1;
        Al[i0] = lp0; Al[i1] = lp1;
    }
    if (tid < 128) { cs[tid] = 0.f; cq[tid] = 0.f; }
    __syncthreads();

    const int wm = wid & 1, wn = wid >> 1;   // 2x4 warp grid, 32x32 per warp
    float acc[2][2][2][4];
#pragma unroll
    for (int im = 0; im < 2; im++)
#pragma unroll
        for (int in = 0; in < 2; in++)
#pragma unroll
            for (int j = 0; j < 2; j++)
#pragma unroll
                for (int v = 0; v < 4; v++) acc[im][in][j][v] = 0.f;

#pragma unroll
    for (int ks = 0; ks < 8; ks++) {
        uint4 ahv[2], alv[2], bhv[2], blv[2];
#pragma unroll
        for (int im = 0; im < 2; im++) {
            int idx = ((ks * 4 + wm * 2 + im) * 32 + (lane ^ ks)) * 4;
            ahv[im] = *reinterpret_cast<const uint4*>(Ah + idx);
            alv[im] = *reinterpret_cast<const uint4*>(Al + idx);
        }
#pragma unroll
        for (int in = 0; in < 2; in++) {
            int idx = ((ks * 8 + wn * 2 + in) * 32 + lane) * 4;
            bhv[in] = *reinterpret_cast<const uint4*>(Bh + idx);
            blv[in] = *reinterpret_cast<const uint4*>(Bl + idx);
        }
#pragma unroll
        for (int im = 0; im < 2; im++)
#pragma unroll
            for (int in = 0; in < 2; in++)
#pragma unroll
                for (int j = 0; j < 2; j++) {
                    uint32_t b0h = j ? bhv[in].z : bhv[in].x;
                    uint32_t b1h = j ? bhv[in].w : bhv[in].y;
                    uint32_t b0l = j ? blv[in].z : blv[in].x;
                    uint32_t b1l = j ? blv[in].w : blv[in].y;
                    MMA_BF16(acc[im][in][j], ahv[im], b0h, b1h);
                    MMA_BF16(acc[im][in][j], ahv[im], b0l, b1l);
                    MMA_BF16(acc[im][in][j], alv[im], b0h, b1h);
                }
    }

    const int tg = lane >> 2, tc = lane & 3;
    float2 bv[2][2];
#pragma unroll
    for (int in = 0; in < 2; in++)
#pragma unroll
        for (int j = 0; j < 2; j++)
            bv[in][j] = __ldg(reinterpret_cast<const float2*>(bias + wn * 32 + in * 16 + j * 8 + tc * 2));

    if (mode == 0) {
#pragma unroll
        for (int im = 0; im < 2; im++)
#pragma unroll
            for (int rh = 0; rh < 2; rh++) {
                int gr = r0 + (wm * 2 + im) * 16 + rh * 8 + tg;
                if (gr < Nn) {
                    float* op = g_t + (size_t)gr * D;
#pragma unroll
                    for (int in = 0; in < 2; in++)
#pragma unroll
                        for (int j = 0; j < 2; j++) {
                            int col = wn * 32 + in * 16 + j * 8 + tc * 2;
                            float2 v;
                            v.x = fmaxf(acc[im][in][j][rh * 2]     + bv[in][j].x, 0.f);
                            v.y = fmaxf(acc[im][in][j][rh * 2 + 1] + bv[in][j].y, 0.f);
                            *reinterpret_cast<float2*>(op + col) = v;
                        }
                }
            }
    } else {
        float s8[8], q8[8];
#pragma unroll
        for (int u = 0; u < 8; u++) { s8[u] = 0.f; q8[u] = 0.f; }
#pragma unroll
        for (int im = 0; im < 2; im++)
#pragma unroll
            for (int rh = 0; rh < 2; rh++) {
                int gr = r0 + (wm * 2 + im) * 16 + rh * 8 + tg;
                if (gr < Nn) {
                    const float* xr = x + (size_t)gr * D;
                    float* op = out + (size_t)gr * D;
#pragma unroll
                    for (int in = 0; in < 2; in++)
#pragma unroll
                        for (int j = 0; j < 2; j++) {
                            int col = wn * 32 + in * 16 + j * 8 + tc * 2;
                            float2 xv = __ldg(reinterpret_cast<const float2*>(xr + col));
                            float v0 = acc[im][in][j][rh * 2]     + bv[in][j].x + xv.x;
                            float v1 = acc[im][in][j][rh * 2 + 1] + bv[in][j].y + xv.y;
                            int ci = in * 4 + j * 2;
                            s8[ci] += v0;     q8[ci] += v0 * v0;
                            s8[ci + 1] += v1; q8[ci + 1] += v1 * v1;
                            *reinterpret_cast<float2*>(op + col) = make_float2(v0, v1);
                        }
                }
            }
#pragma unroll
        for (int in = 0; in < 2; in++)
#pragma unroll
            for (int j = 0; j < 2; j++)
#pragma unroll
                for (int h = 0; h < 2; h++) {
                    int col = wn * 32 + in * 16 + j * 8 + tc * 2 + h;
                    int ci = in * 4 + j * 2 + h;
                    atomicAdd(&cs[col], s8[ci]);
                    atomicAdd(&cq[col], q8[ci]);
                }
        __syncthreads();
        if (tid < 128) {
            atomicAdd(&g_stats[tid],     cs[tid]);
            atomicAdd(&g_stats[D + tid], cq[tid]);
        }
    }
}

// ---------------------------------------------------------------------------
// BN: per-block recompute of scale/shift from stats, then in-place apply.
// ---------------------------------------------------------------------------
__global__ void bn_kernel(float* __restrict__ out,
                          const float* __restrict__ bn_w,
                          const float* __restrict__ bn_b) {
    __shared__ float sc_s[D], sh_s[D];
    int tid = threadIdx.x;
    if (tid < D) {
        float inv_n = 1.f / (float)Nn;
        float mean  = g_stats[tid] * inv_n;
        float var   = g_stats[D + tid] * inv_n - mean * mean;
        float rstd  = rsqrtf(var + 1e-5f);
        float sc    = rstd * __ldg(bn_w + tid);
        sc_s[tid] = sc;
        sh_s[tid] = __ldg(bn_b + tid) - mean * sc;
    }
    __syncthreads();
    size_t stride = (size_t)gridDim.x * blockDim.x;
    size_t total  = (size_t)Nn * 32;
    for (size_t v = (size_t)blockIdx.x * blockDim.x + tid; v < total; v += stride) {
        int q = (int)(v & 31);
        float4 h = reinterpret_cast<float4*>(out)[v];
        float4 sc = *reinterpret_cast<const float4*>(sc_s + q * 4);
        float4 sh = *reinterpret_cast<const float4*>(sh_s + q * 4);
        h.x = h.x * sc.x + sh.x;
        h.y = h.y * sc.y + sh.y;
        h.z = h.z * sc.z + sh.z;
        h.w = h.w * sc.w + sh.w;
        reinterpret_cast<float4*>(out)[v] = h;
    }
}

// ---------------------------------------------------------------------------
extern "C" void kernel_launch(void* const* d_in, const int* in_sizes, int n_in,
                              void* d_out, int out_size) {
    const float* x   = (const float*)d_in[0];
    const int*   ei  = (const int*)d_in[1];
    const float* ea  = (const float*)d_in[2];
    const float* W1  = (const float*)d_in[3];
    const float* b1  = (const float*)d_in[4];
    const float* W2  = (const float*)d_in[5];
    const float* b2  = (const float*)d_in[6];
    const float* bnw = (const float*)d_in[7];
    const float* bnb = (const float*)d_in[8];
    float* out = (float*)d_out;

    init_kernel<<<2 + (Nn + 255) / 256, 256>>>(W1, W2);   // (1) prep + zero
    hist_kernel<<<(E + 255) / 256, 256>>>(ei);            // (2)
    scan_kernel<<<SCAN_G, SCAN_B>>>();                    // (3) fused scan
    scatter_kernel<<<(E + 255) / 256, 256>>>(ei);         // (4) <- ncu window
    aggregate_kernel<<<(Nn * 32 + 255) / 256, 256>>>(x, ea); // (5) <- ncu window

    int smem_bytes = (4096 * 2 + 8192 * 2 + 256) * 4;     // 99,328 B
    cudaFuncSetAttribute(mlp_tc, cudaFuncAttributeMaxDynamicSharedMemorySize, smem_bytes);
    int grid = (Nn + 63) / 64;
    mlp_tc<<<grid, 256, smem_bytes>>>(x, b1, nullptr, 0); // (6) <- ncu window
    mlp_tc<<<grid, 256, smem_bytes>>>(x, b2, out, 1);     // (7)

    bn_kernel<<<1024, 256>>>(out, bnw, bnb);              // (8)
}